// round 7
// baseline (speedup 1.0000x reference)
#include <cuda_runtime.h>
#include <math.h>
#include <stdint.h>

#define NN    50000
#define EE    600000
#define DD    128
#define RREL2 474          /* 2R */
#define QQ    128
#define KTOT  1664         /* 13*D */
#define RELSZ (RREL2*DD)   /* 60672 */
#define NKT   52           /* K tiles of 32 */

// -------- scratch (static device globals; no allocation allowed) --------
__device__ __align__(16) float    g_rel[RELSZ];
__device__ int      g_row_start[NN + 1];
__device__ int      g_cursor[NN];
__device__ unsigned g_packed[EE];                 // src (16b) | attr<<16
__device__ __align__(16) float    g_feat4[(size_t)NN * 4 * DD]; // F [N,512]
__device__ float    g_logdeg[NN];
__device__ float    g_logdeg_mean;
// Wlin permuted to grouped-K, tile-major [kt][k][j], fp32:
__device__ __align__(16) float    g_wB[NKT * 4096];

// ========================= helpers ==========================
__device__ __forceinline__ void fma2(unsigned long long& d,
                                     unsigned long long a, unsigned long long b) {
    asm("fma.rn.f32x2 %0, %1, %2, %0;" : "+l"(d) : "l"(a), "l"(b));
}
__device__ __forceinline__ unsigned long long splat2(float x) {
    unsigned long long r;
    asm("mov.b64 %0, {%1, %1};" : "=l"(r) : "f"(x));
    return r;
}
__device__ __forceinline__ float2 unpack2(unsigned long long v) {
    float2 r;
    asm("mov.b64 {%0, %1}, %2;" : "=f"(r.x), "=f"(r.y) : "l"(v));
    return r;
}
__device__ __forceinline__ uint32_t smem_u32(const void* p) {
    uint32_t a;
    asm("{ .reg .u64 t; cvta.to.shared.u64 t, %1; cvt.u32.u64 %0, t; }"
        : "=r"(a) : "l"(p));
    return a;
}
__device__ __forceinline__ void cp16(uint32_t s, const void* g) {
    asm volatile("cp.async.cg.shared.global [%0], [%1], 16;" :: "r"(s), "l"(g));
}
#define CP_COMMIT() asm volatile("cp.async.commit_group;" ::: "memory")
#define CP_WAIT0()  asm volatile("cp.async.wait_group 0;" ::: "memory")

// ======================= K1: rel = query @ Wr^T + br =======================
__global__ void rel_kernel(const float* __restrict__ Wr,
                           const float* __restrict__ br,
                           const float* __restrict__ query) {
    int warp = (blockIdx.x * blockDim.x + threadIdx.x) >> 5;
    int lane = threadIdx.x & 31;
    if (warp >= RELSZ) return;
    const float* w = Wr + (size_t)warp * QQ;
    float s = w[lane]      * __ldg(&query[lane])
            + w[lane + 32] * __ldg(&query[lane + 32])
            + w[lane + 64] * __ldg(&query[lane + 64])
            + w[lane + 96] * __ldg(&query[lane + 96]);
    #pragma unroll
    for (int o = 16; o; o >>= 1) s += __shfl_xor_sync(0xffffffffu, s, o);
    if (lane == 0) g_rel[warp] = s + br[warp];
}

// ==== K2: exclusive scan of degree -> row_start/cursor, + logdeg & mean ====
__global__ void scan_kernel(const float* __restrict__ degout) {
    __shared__ int   wsum[32];
    __shared__ int   carry;
    __shared__ float fsh[1024];
    int t = threadIdx.x, lane = t & 31, w = t >> 5;
    if (t == 0) carry = 0;
    float lsum = 0.f;
    __syncthreads();
    for (int base = 0; base < NN; base += 1024) {
        int i = base + t;
        float dgf = (i < NN) ? degout[i] : 0.f;
        if (i < NN) {
            float ld = logf(dgf + 1.0f);
            g_logdeg[i] = ld;
            lsum += ld;
        }
        int v = (i < NN) ? (int)(dgf + 0.5f) : 0;
        int x = v;
        #pragma unroll
        for (int o = 1; o < 32; o <<= 1) {
            int y = __shfl_up_sync(0xffffffffu, x, o);
            if (lane >= o) x += y;
        }
        if (lane == 31) wsum[w] = x;
        __syncthreads();
        if (w == 0) {
            int s = wsum[lane];
            #pragma unroll
            for (int o = 1; o < 32; o <<= 1) {
                int y = __shfl_up_sync(0xffffffffu, s, o);
                if (lane >= o) s += y;
            }
            wsum[lane] = s;
        }
        __syncthreads();
        int excl = x - v + (w ? wsum[w - 1] : 0) + carry;
        if (i < NN) { g_row_start[i] = excl; g_cursor[i] = excl; }
        __syncthreads();
        if (t == 1023) carry = excl + v;
        __syncthreads();
    }
    if (t == 0) g_row_start[NN] = carry;
    // block-wide mean of logdeg
    fsh[t] = lsum;
    __syncthreads();
    for (int o = 512; o; o >>= 1) {
        if (t < o) fsh[t] += fsh[t + o];
        __syncthreads();
    }
    if (t == 0) g_logdeg_mean = fsh[0] / (float)NN;
}

// ================= K3: bucket edges into CSR slots ========================
__global__ void fill_kernel(const int* __restrict__ ei,
                            const int* __restrict__ ea) {
    int e = blockIdx.x * blockDim.x + threadIdx.x;
    if (e >= EE) return;
    int src = ei[e];
    int dst = ei[EE + e];
    int a   = ea[e];
    int pos = atomicAdd(&g_cursor[dst], 1);
    g_packed[pos] = (unsigned)src | ((unsigned)a << 16);
}

// ===== K4: permute Wlin to grouped-K tile-major [kt][k][j], fp32 =====
// grouped col cp: cp<128 -> c=cp ; else m=cp-128, s=m>>9, fidx=m&511, c=128+3*fidx+s
__global__ void wperm_kernel(const float* __restrict__ Wlin) {
    __shared__ float tmp[32 * 129];
    int kt = blockIdx.x;
    int t  = threadIdx.x;
    #pragma unroll
    for (int i = 0; i < 16; i++) {
        int e  = t + i * 256;          // 0..4095
        int j  = e >> 5;
        int kl = e & 31;
        int cp = kt * 32 + kl;
        int c;
        if (cp < 128) c = cp;
        else { int m = cp - 128; int s = m >> 9; int f = m & 511; c = 128 + 3 * f + s; }
        tmp[kl * 129 + j] = Wlin[(size_t)j * KTOT + c];
    }
    __syncthreads();
    #pragma unroll
    for (int i = 0; i < 16; i++) {
        int e = t + i * 256;
        g_wB[(size_t)kt * 4096 + e] = tmp[(e >> 7) * 129 + (e & 127)];
    }
}

// ====== K5: per-node gather reduction, float4 per lane (cols 4l..4l+3) ======
__global__ void agg_kernel(const float* __restrict__ nf,
                           const float* __restrict__ boundary,
                           const float* __restrict__ degout) {
    int n    = (blockIdx.x * blockDim.x + threadIdx.x) >> 5;
    int lane = threadIdx.x & 31;
    if (n >= NN) return;
    int beg = g_row_start[n], end = g_row_start[n + 1];
    int c0 = lane * 4;

    float4 sum = make_float4(0.f, 0.f, 0.f, 0.f);
    float4 sq  = make_float4(0.f, 0.f, 0.f, 0.f);
    float4 mx  = make_float4(-INFINITY, -INFINITY, -INFINITY, -INFINITY);
    float4 mn  = make_float4(INFINITY, INFINITY, INFINITY, INFINITY);

    for (int e = beg; e < end; e++) {
        unsigned p = g_packed[e];
        float4 s4 = *(const float4*)(nf    + (size_t)(p & 0xFFFFu) * DD + c0);
        float4 f4 = *(const float4*)(g_rel + (size_t)(p >> 16) * DD + c0);
        float m0 = s4.x * f4.x, m1 = s4.y * f4.y, m2 = s4.z * f4.z, m3 = s4.w * f4.w;
        sum.x += m0; sum.y += m1; sum.z += m2; sum.w += m3;
        sq.x += m0 * m0; sq.y += m1 * m1; sq.z += m2 * m2; sq.w += m3 * m3;
        mx.x = fmaxf(mx.x, m0); mx.y = fmaxf(mx.y, m1);
        mx.z = fmaxf(mx.z, m2); mx.w = fmaxf(mx.w, m3);
        mn.x = fminf(mn.x, m0); mn.y = fminf(mn.y, m1);
        mn.z = fminf(mn.z, m2); mn.w = fminf(mn.w, m3);
    }

    float d0  = degout[n];
    float deg = d0 + 1.0f;
    bool  has_edge = (d0 > 0.0f);
    float inv = 1.0f / deg;
    float4 b = *(const float4*)(boundary + (size_t)n * DD + c0);

    float sums[4] = {sum.x, sum.y, sum.z, sum.w};
    float sqs[4]  = {sq.x, sq.y, sq.z, sq.w};
    float mxs[4]  = {mx.x, mx.y, mx.z, mx.w};
    float mns[4]  = {mn.x, mn.y, mn.z, mn.w};
    float bs[4]   = {b.x, b.y, b.z, b.w};

    #pragma unroll
    for (int u = 0; u < 4; u++) {
        float bb = bs[u];
        float mean   = (sums[u] + bb) * inv;
        float sqmean = (sqs[u] + bb * bb) * inv;
        float vmx = has_edge ? mxs[u] : 0.0f;
        float vmn = has_edge ? mns[u] : 0.0f;
        vmx = fmaxf(vmx, bb);
        vmn = fminf(vmn, bb);
        float sd = sqrtf(fmaxf(sqmean - mean * mean, 1e-6f));
        float4 v = make_float4(mean, vmx, vmn, sd);
        *(float4*)&g_feat4[(size_t)n * 512 + (c0 + u) * 4] = v;
    }
}

// ================== K6: SIMT f32x2 GEMM, fused epilogue =====================
// 128x128 tile, BK=32, 256 threads, 8x8 per thread (j-packed f32x2 accs).
// A stored PRE-SPLATTED in smem as u64 pairs -> LDS.64 gives both FFMA2 halves.
// ASTR must be EVEN: row byte stride = ASTR*8 must be 16B-aligned for ST.128.
#define ASTR 34                           /* u64 stride per A row (even!) */
#define SM_BS_BYTES  32768                /* Bs: 2 x 32 x 128 f32 */
#define SM_AS_OFF    32768                /* As2: 128 x ASTR u64  */
#define SM_AS_BYTES  (128 * ASTR * 8)
#define SM_SC_OFF    (SM_AS_OFF + SM_AS_BYTES)
#define SMEM_BYTES   (SM_SC_OFF + 1024)

__global__ void __launch_bounds__(256)
gemm_simt(const float* __restrict__ nf,
          const float* __restrict__ blin,
          float* __restrict__ out) {
    extern __shared__ char smc[];
    float*              Bs  = (float*)smc;                       // [2][32*128]
    unsigned long long* As2 = (unsigned long long*)(smc + SM_AS_OFF);
    float*              sc1 = (float*)(smc + SM_SC_OFF);
    float*              sc2 = sc1 + 128;

    const int t  = threadIdx.x;
    const int n0 = blockIdx.x * 128;
    const int tx = t & 15;
    const int ty = t >> 4;
    const int cq = t & 7;            // c-quad for A build
    const int nl = t >> 3;           // base n_local for A build (stride 32 over i)

    if (t < 128) {
        int n = n0 + t;
        float scale = 0.f;
        if (n < NN) scale = g_logdeg[n] / (g_logdeg_mean + 1e-10f);
        sc1[t] = scale;
        sc2[t] = 1.0f / fmaxf(scale, 0.01f);
    }
    __syncthreads();

    const uint32_t bsAddr = smem_u32(Bs);

    // ---- A tile prefetch into registers (grouped-K virtual X) ----
    float4 av[4];
    auto ldA = [&](int kt) {
        int grp = (kt >= 36) ? 3 : (kt >= 20) ? 2 : (kt >= 4) ? 1 : 0;
        #pragma unroll
        for (int i = 0; i < 4; i++) {
            int nli = nl + i * 32;
            int n = n0 + nli;
            float4 v = make_float4(0.f, 0.f, 0.f, 0.f);
            if (n < NN) {
                if (grp == 0) {
                    v = *(const float4*)&nf[(size_t)n * DD + kt * 32 + cq * 4];
                } else {
                    int f0 = kt * 32 - ((grp == 3) ? 1152 : (grp == 2) ? 640 : 128);
                    v = *(const float4*)&g_feat4[(size_t)n * 512 + f0 + cq * 4];
                    if (grp >= 2) {
                        float s = (grp == 3) ? sc2[nli] : sc1[nli];
                        v.x *= s; v.y *= s; v.z *= s; v.w *= s;
                    }
                }
            }
            av[i] = v;
        }
    };
    auto stA = [&]() {
        #pragma unroll
        for (int i = 0; i < 4; i++) {
            unsigned long long* dst = &As2[(size_t)(nl + i * 32) * ASTR + cq * 4];
            ulonglong2 p0, p1;
            p0.x = splat2(av[i].x); p0.y = splat2(av[i].y);
            p1.x = splat2(av[i].z); p1.y = splat2(av[i].w);
            *(ulonglong2*)(dst)     = p0;
            *(ulonglong2*)(dst + 2) = p1;
        }
    };
    auto ldB = [&](int kt, int buf) {
        const float* src = &g_wB[(size_t)kt * 4096];
        uint32_t dst = bsAddr + buf * 16384 + t * 16;
        #pragma unroll
        for (int i = 0; i < 4; i++)
            cp16(dst + i * 4096, src + t * 4 + i * 1024);
        CP_COMMIT();
    };

    unsigned long long acc[8][4];
    #pragma unroll
    for (int r = 0; r < 8; r++)
        #pragma unroll
        for (int p = 0; p < 4; p++) acc[r][p] = 0ull;

    ldA(0);
    ldB(0, 0);
    stA();
    CP_WAIT0();
    __syncthreads();

    int cur = 0;
    for (int kt = 0; kt < NKT; kt++) {
        if (kt + 1 < NKT) {
            ldA(kt + 1);
            ldB(kt + 1, cur ^ 1);
        }
        const float* Bc = &Bs[cur * 4096];
        #pragma unroll 4
        for (int kl = 0; kl < 32; kl++) {
            unsigned long long a2[8];
            #pragma unroll
            for (int r = 0; r < 4; r++) {
                a2[r]     = As2[(ty * 4 + r) * ASTR + kl];
                a2[r + 4] = As2[(ty * 4 + 64 + r) * ASTR + kl];
            }
            ulonglong2 b01 = *(const ulonglong2*)&Bc[kl * 128 + tx * 4];
            ulonglong2 b23 = *(const ulonglong2*)&Bc[kl * 128 + tx * 4 + 64];
            #pragma unroll
            for (int r = 0; r < 8; r++) {
                fma2(acc[r][0], a2[r], b01.x);
                fma2(acc[r][1], a2[r], b01.y);
                fma2(acc[r][2], a2[r], b23.x);
                fma2(acc[r][3], a2[r], b23.y);
            }
        }
        __syncthreads();           // everyone done reading As2/Bs[cur]
        if (kt + 1 < NKT) {
            stA();
            CP_WAIT0();
        }
        __syncthreads();
        cur ^= 1;
    }

    // ---- epilogue: bias + relu ----
    float4 bl0 = __ldg((const float4*)&blin[tx * 4]);
    float4 bl1 = __ldg((const float4*)&blin[tx * 4 + 64]);
    #pragma unroll
    for (int r = 0; r < 8; r++) {
        int n = n0 + ty * 4 + ((r < 4) ? r : (64 + r - 4));
        if (n >= NN) continue;
        float2 p0 = unpack2(acc[r][0]);
        float2 p1 = unpack2(acc[r][1]);
        float2 p2 = unpack2(acc[r][2]);
        float2 p3 = unpack2(acc[r][3]);
        float4 o0, o1;
        o0.x = fmaxf(p0.x + bl0.x, 0.f);
        o0.y = fmaxf(p0.y + bl0.y, 0.f);
        o0.z = fmaxf(p1.x + bl0.z, 0.f);
        o0.w = fmaxf(p1.y + bl0.w, 0.f);
        o1.x = fmaxf(p2.x + bl1.x, 0.f);
        o1.y = fmaxf(p2.y + bl1.y, 0.f);
        o1.z = fmaxf(p3.x + bl1.z, 0.f);
        o1.w = fmaxf(p3.y + bl1.w, 0.f);
        *(float4*)&out[(size_t)n * DD + tx * 4]      = o0;
        *(float4*)&out[(size_t)n * DD + tx * 4 + 64] = o1;
    }
}

// ============================== launch ====================================
extern "C" void kernel_launch(void* const* d_in, const int* in_sizes, int n_in,
                              void* d_out, int out_size) {
    const float* nf    = (const float*)d_in[0];   // node_features [N,D]
    const float* query = (const float*)d_in[1];   // [1,Q]
    const float* bnd   = (const float*)d_in[2];   // boundary [N,D]
    const float* deg   = (const float*)d_in[3];   // degree_out [N]
    const float* Wr    = (const float*)d_in[4];   // [2R*D, Q]
    const float* br    = (const float*)d_in[5];   // [2R*D]
    const float* Wlin  = (const float*)d_in[6];   // [D, 13D]
    const float* blin  = (const float*)d_in[7];   // [D]
    const int*   ei    = (const int*)d_in[8];     // edge_index [2,E] int32
    const int*   ea    = (const int*)d_in[9];     // edge_attr [E] int32
    float*       out   = (float*)d_out;           // [N,D]

    cudaFuncSetAttribute(gemm_simt, cudaFuncAttributeMaxDynamicSharedMemorySize,
                         SMEM_BYTES);

    // launch order places gemm_simt at index 5 so ncu (-s 5 -c 1) profiles it
    rel_kernel  <<<(RELSZ * 32 + 255) / 256, 256>>>(Wr, br, query);  // 0
    scan_kernel <<<1, 1024>>>(deg);                                   // 1
    fill_kernel <<<(EE + 255) / 256, 256>>>(ei, ea);                  // 2
    wperm_kernel<<<NKT, 256>>>(Wlin);                                 // 3
    agg_kernel  <<<(NN * 32 + 255) / 256, 256>>>(nf, bnd, deg);       // 4
    gemm_simt   <<<(NN + 127) / 128, 256, SMEM_BYTES>>>(nf, blin, out); // 5
}

// round 8
// speedup vs baseline: 1.1347x; 1.1347x over previous
#include <cuda_runtime.h>
#include <math.h>
#include <stdint.h>

#define NN    50000
#define EE    600000
#define DD    128
#define RREL2 474          /* 2R */
#define QQ    128
#define KTOT  1664         /* 13*D */
#define RELSZ (RREL2*DD)   /* 60672 */
#define NKT   52           /* K tiles of 32 */

// -------- scratch (static device globals; no allocation allowed) --------
__device__ __align__(16) float    g_rel[RELSZ];
__device__ int      g_row_start[NN + 1];
__device__ int      g_cursor[NN];
__device__ unsigned g_packed[EE];                 // src (16b) | attr<<16
__device__ __align__(16) float    g_feat4[(size_t)NN * 4 * DD]; // F [N,512]
__device__ float    g_logdeg[NN];
__device__ float    g_logdeg_mean;
// Wlin permuted to grouped-K, tile-major [kt][k][j], fp32:
__device__ __align__(16) float    g_wB[NKT * 4096];

// ========================= helpers ==========================
__device__ __forceinline__ void fma2(unsigned long long& d,
                                     unsigned long long a, unsigned long long b) {
    asm("fma.rn.f32x2 %0, %1, %2, %0;" : "+l"(d) : "l"(a), "l"(b));
}
__device__ __forceinline__ unsigned long long splat2(float x) {
    unsigned long long r;
    asm("mov.b64 %0, {%1, %1};" : "=l"(r) : "f"(x));
    return r;
}
__device__ __forceinline__ float2 unpack2(unsigned long long v) {
    float2 r;
    asm("mov.b64 {%0, %1}, %2;" : "=f"(r.x), "=f"(r.y) : "l"(v));
    return r;
}
__device__ __forceinline__ uint32_t smem_u32(const void* p) {
    uint32_t a;
    asm("{ .reg .u64 t; cvta.to.shared.u64 t, %1; cvt.u32.u64 %0, t; }"
        : "=r"(a) : "l"(p));
    return a;
}
__device__ __forceinline__ void cp16(uint32_t s, const void* g) {
    asm volatile("cp.async.cg.shared.global [%0], [%1], 16;" :: "r"(s), "l"(g));
}
#define CP_COMMIT() asm volatile("cp.async.commit_group;" ::: "memory")
#define CP_WAIT0()  asm volatile("cp.async.wait_group 0;" ::: "memory")

// ======================= K1: rel = query @ Wr^T + br =======================
__global__ void rel_kernel(const float* __restrict__ Wr,
                           const float* __restrict__ br,
                           const float* __restrict__ query) {
    int warp = (blockIdx.x * blockDim.x + threadIdx.x) >> 5;
    int lane = threadIdx.x & 31;
    if (warp >= RELSZ) return;
    const float* w = Wr + (size_t)warp * QQ;
    float s = w[lane]      * __ldg(&query[lane])
            + w[lane + 32] * __ldg(&query[lane + 32])
            + w[lane + 64] * __ldg(&query[lane + 64])
            + w[lane + 96] * __ldg(&query[lane + 96]);
    #pragma unroll
    for (int o = 16; o; o >>= 1) s += __shfl_xor_sync(0xffffffffu, s, o);
    if (lane == 0) g_rel[warp] = s + br[warp];
}

// ==== K2: exclusive scan of degree -> row_start/cursor, + logdeg & mean ====
__global__ void scan_kernel(const float* __restrict__ degout) {
    __shared__ int   wsum[32];
    __shared__ int   carry;
    __shared__ float fsh[1024];
    int t = threadIdx.x, lane = t & 31, w = t >> 5;
    if (t == 0) carry = 0;
    float lsum = 0.f;
    __syncthreads();
    for (int base = 0; base < NN; base += 1024) {
        int i = base + t;
        float dgf = (i < NN) ? degout[i] : 0.f;
        if (i < NN) {
            float ld = logf(dgf + 1.0f);
            g_logdeg[i] = ld;
            lsum += ld;
        }
        int v = (i < NN) ? (int)(dgf + 0.5f) : 0;
        int x = v;
        #pragma unroll
        for (int o = 1; o < 32; o <<= 1) {
            int y = __shfl_up_sync(0xffffffffu, x, o);
            if (lane >= o) x += y;
        }
        if (lane == 31) wsum[w] = x;
        __syncthreads();
        if (w == 0) {
            int s = wsum[lane];
            #pragma unroll
            for (int o = 1; o < 32; o <<= 1) {
                int y = __shfl_up_sync(0xffffffffu, s, o);
                if (lane >= o) s += y;
            }
            wsum[lane] = s;
        }
        __syncthreads();
        int excl = x - v + (w ? wsum[w - 1] : 0) + carry;
        if (i < NN) { g_row_start[i] = excl; g_cursor[i] = excl; }
        __syncthreads();
        if (t == 1023) carry = excl + v;
        __syncthreads();
    }
    if (t == 0) g_row_start[NN] = carry;
    // block-wide mean of logdeg
    fsh[t] = lsum;
    __syncthreads();
    for (int o = 512; o; o >>= 1) {
        if (t < o) fsh[t] += fsh[t + o];
        __syncthreads();
    }
    if (t == 0) g_logdeg_mean = fsh[0] / (float)NN;
}

// ================= K3: bucket edges into CSR slots ========================
__global__ void fill_kernel(const int* __restrict__ ei,
                            const int* __restrict__ ea) {
    int e = blockIdx.x * blockDim.x + threadIdx.x;
    if (e >= EE) return;
    int src = ei[e];
    int dst = ei[EE + e];
    int a   = ea[e];
    int pos = atomicAdd(&g_cursor[dst], 1);
    g_packed[pos] = (unsigned)src | ((unsigned)a << 16);
}

// ===== K4: permute Wlin to grouped-K tile-major [kt][k][j], fp32 =====
// grouped col cp: cp<128 -> c=cp ; else m=cp-128, s=m>>9, fidx=m&511, c=128+3*fidx+s
__global__ void wperm_kernel(const float* __restrict__ Wlin) {
    __shared__ float tmp[32 * 129];
    int kt = blockIdx.x;
    int t  = threadIdx.x;
    #pragma unroll
    for (int i = 0; i < 16; i++) {
        int e  = t + i * 256;          // 0..4095
        int j  = e >> 5;
        int kl = e & 31;
        int cp = kt * 32 + kl;
        int c;
        if (cp < 128) c = cp;
        else { int m = cp - 128; int s = m >> 9; int f = m & 511; c = 128 + 3 * f + s; }
        tmp[kl * 129 + j] = Wlin[(size_t)j * KTOT + c];
    }
    __syncthreads();
    #pragma unroll
    for (int i = 0; i < 16; i++) {
        int e = t + i * 256;
        g_wB[(size_t)kt * 4096 + e] = tmp[(e >> 7) * 129 + (e & 127)];
    }
}

// ====== K5: per-node gather reduction, float4 per lane (cols 4l..4l+3) ======
__global__ void agg_kernel(const float* __restrict__ nf,
                           const float* __restrict__ boundary,
                           const float* __restrict__ degout) {
    int n    = (blockIdx.x * blockDim.x + threadIdx.x) >> 5;
    int lane = threadIdx.x & 31;
    if (n >= NN) return;
    int beg = g_row_start[n], end = g_row_start[n + 1];
    int c0 = lane * 4;

    float4 sum = make_float4(0.f, 0.f, 0.f, 0.f);
    float4 sq  = make_float4(0.f, 0.f, 0.f, 0.f);
    float4 mx  = make_float4(-INFINITY, -INFINITY, -INFINITY, -INFINITY);
    float4 mn  = make_float4(INFINITY, INFINITY, INFINITY, INFINITY);

    for (int e = beg; e < end; e++) {
        unsigned p = g_packed[e];
        float4 s4 = *(const float4*)(nf    + (size_t)(p & 0xFFFFu) * DD + c0);
        float4 f4 = *(const float4*)(g_rel + (size_t)(p >> 16) * DD + c0);
        float m0 = s4.x * f4.x, m1 = s4.y * f4.y, m2 = s4.z * f4.z, m3 = s4.w * f4.w;
        sum.x += m0; sum.y += m1; sum.z += m2; sum.w += m3;
        sq.x += m0 * m0; sq.y += m1 * m1; sq.z += m2 * m2; sq.w += m3 * m3;
        mx.x = fmaxf(mx.x, m0); mx.y = fmaxf(mx.y, m1);
        mx.z = fmaxf(mx.z, m2); mx.w = fmaxf(mx.w, m3);
        mn.x = fminf(mn.x, m0); mn.y = fminf(mn.y, m1);
        mn.z = fminf(mn.z, m2); mn.w = fminf(mn.w, m3);
    }

    float d0  = degout[n];
    float deg = d0 + 1.0f;
    bool  has_edge = (d0 > 0.0f);
    float inv = 1.0f / deg;
    float4 b = *(const float4*)(boundary + (size_t)n * DD + c0);

    float sums[4] = {sum.x, sum.y, sum.z, sum.w};
    float sqs[4]  = {sq.x, sq.y, sq.z, sq.w};
    float mxs[4]  = {mx.x, mx.y, mx.z, mx.w};
    float mns[4]  = {mn.x, mn.y, mn.z, mn.w};
    float bs[4]   = {b.x, b.y, b.z, b.w};

    #pragma unroll
    for (int u = 0; u < 4; u++) {
        float bb = bs[u];
        float mean   = (sums[u] + bb) * inv;
        float sqmean = (sqs[u] + bb * bb) * inv;
        float vmx = has_edge ? mxs[u] : 0.0f;
        float vmn = has_edge ? mns[u] : 0.0f;
        vmx = fmaxf(vmx, bb);
        vmn = fminf(vmn, bb);
        float sd = sqrtf(fmaxf(sqmean - mean * mean, 1e-6f));
        float4 v = make_float4(mean, vmx, vmn, sd);
        *(float4*)&g_feat4[(size_t)n * 512 + (c0 + u) * 4] = v;
    }
}

// ================== K6: SIMT f32x2 GEMM, fused epilogue =====================
// 128x128 tile, BK=32, 256 threads, 8x8 per thread (j-packed f32x2 accs).
// R5-proven structure: A as float4 in smem, splat in inner loop (fma-bound,
// splats hide under fma pipe). __launch_bounds__(256,2) targets 2 CTAs/SM.
#define ASTR 36
#define SM_AS  8192              /* floats: Bs = 2*4096 */
#define SM_SC  (8192 + 128 * ASTR)
#define SMEM_F (SM_SC + 256)
#define SMEM_BYTES (SMEM_F * 4)

__global__ void __launch_bounds__(256, 2)
gemm_simt(const float* __restrict__ nf,
          const float* __restrict__ blin,
          float* __restrict__ out) {
    extern __shared__ float sm[];
    float* Bs  = sm;                 // [2][32*128]
    float* As  = sm + SM_AS;         // [128][ASTR]
    float* sc1 = sm + SM_SC;
    float* sc2 = sc1 + 128;

    const int t  = threadIdx.x;
    const int n0 = blockIdx.x * 128;
    const int tx = t & 15;
    const int ty = t >> 4;
    const int cq = t & 7;            // c-quad for A build
    const int nl = t >> 3;           // base n_local for A build (stride 32 over i)

    if (t < 128) {
        int n = n0 + t;
        float scale = 0.f;
        if (n < NN) scale = g_logdeg[n] / (g_logdeg_mean + 1e-10f);
        sc1[t] = scale;
        sc2[t] = 1.0f / fmaxf(scale, 0.01f);
    }
    __syncthreads();

    const uint32_t bsAddr = smem_u32(Bs);

    // ---- A tile prefetch into registers (grouped-K virtual X) ----
    float4 av[4];
    auto ldA = [&](int kt) {
        int grp = (kt >= 36) ? 3 : (kt >= 20) ? 2 : (kt >= 4) ? 1 : 0;
        #pragma unroll
        for (int i = 0; i < 4; i++) {
            int nli = nl + i * 32;
            int n = n0 + nli;
            float4 v = make_float4(0.f, 0.f, 0.f, 0.f);
            if (n < NN) {
                if (grp == 0) {
                    v = *(const float4*)&nf[(size_t)n * DD + kt * 32 + cq * 4];
                } else {
                    int f0 = kt * 32 - ((grp == 3) ? 1152 : (grp == 2) ? 640 : 128);
                    v = *(const float4*)&g_feat4[(size_t)n * 512 + f0 + cq * 4];
                    if (grp >= 2) {
                        float s = (grp == 3) ? sc2[nli] : sc1[nli];
                        v.x *= s; v.y *= s; v.z *= s; v.w *= s;
                    }
                }
            }
            av[i] = v;
        }
    };
    auto stA = [&]() {
        #pragma unroll
        for (int i = 0; i < 4; i++)
            *(float4*)&As[(nl + i * 32) * ASTR + cq * 4] = av[i];
    };
    auto ldB = [&](int kt, int buf) {
        const float* src = &g_wB[(size_t)kt * 4096];
        uint32_t dst = bsAddr + buf * 16384 + t * 16;
        #pragma unroll
        for (int i = 0; i < 4; i++)
            cp16(dst + i * 4096, src + t * 4 + i * 1024);
        CP_COMMIT();
    };

    unsigned long long acc[8][4];
    #pragma unroll
    for (int r = 0; r < 8; r++)
        #pragma unroll
        for (int p = 0; p < 4; p++) acc[r][p] = 0ull;

    ldA(0);
    ldB(0, 0);
    stA();
    CP_WAIT0();
    __syncthreads();

    int cur = 0;
    for (int kt = 0; kt < NKT; kt++) {
        if (kt + 1 < NKT) {
            ldA(kt + 1);
            ldB(kt + 1, cur ^ 1);
        }
        const float* Bc = &Bs[cur * 4096];
        #pragma unroll 4
        for (int kl = 0; kl < 32; kl++) {
            unsigned long long a2[8];
            #pragma unroll
            for (int r = 0; r < 4; r++) {
                a2[r]     = splat2(As[(ty * 4 + r) * ASTR + kl]);
                a2[r + 4] = splat2(As[(ty * 4 + 64 + r) * ASTR + kl]);
            }
            ulonglong2 b01 = *(const ulonglong2*)&Bc[kl * 128 + tx * 4];
            ulonglong2 b23 = *(const ulonglong2*)&Bc[kl * 128 + tx * 4 + 64];
            #pragma unroll
            for (int r = 0; r < 8; r++) {
                fma2(acc[r][0], a2[r], b01.x);
                fma2(acc[r][1], a2[r], b01.y);
                fma2(acc[r][2], a2[r], b23.x);
                fma2(acc[r][3], a2[r], b23.y);
            }
        }
        __syncthreads();           // everyone done reading As/Bs[cur]
        if (kt + 1 < NKT) {
            stA();
            CP_WAIT0();
        }
        __syncthreads();
        cur ^= 1;
    }

    // ---- epilogue: bias + relu ----
    float4 bl0 = __ldg((const float4*)&blin[tx * 4]);
    float4 bl1 = __ldg((const float4*)&blin[tx * 4 + 64]);
    #pragma unroll
    for (int r = 0; r < 8; r++) {
        int n = n0 + ty * 4 + ((r < 4) ? r : (64 + r - 4));
        if (n >= NN) continue;
        float2 p0 = unpack2(acc[r][0]);
        float2 p1 = unpack2(acc[r][1]);
        float2 p2 = unpack2(acc[r][2]);
        float2 p3 = unpack2(acc[r][3]);
        float4 o0, o1;
        o0.x = fmaxf(p0.x + bl0.x, 0.f);
        o0.y = fmaxf(p0.y + bl0.y, 0.f);
        o0.z = fmaxf(p1.x + bl0.z, 0.f);
        o0.w = fmaxf(p1.y + bl0.w, 0.f);
        o1.x = fmaxf(p2.x + bl1.x, 0.f);
        o1.y = fmaxf(p2.y + bl1.y, 0.f);
        o1.z = fmaxf(p3.x + bl1.z, 0.f);
        o1.w = fmaxf(p3.y + bl1.w, 0.f);
        *(float4*)&out[(size_t)n * DD + tx * 4]      = o0;
        *(float4*)&out[(size_t)n * DD + tx * 4 + 64] = o1;
    }
}

// ============================== launch ====================================
extern "C" void kernel_launch(void* const* d_in, const int* in_sizes, int n_in,
                              void* d_out, int out_size) {
    const float* nf    = (const float*)d_in[0];   // node_features [N,D]
    const float* query = (const float*)d_in[1];   // [1,Q]
    const float* bnd   = (const float*)d_in[2];   // boundary [N,D]
    const float* deg   = (const float*)d_in[3];   // degree_out [N]
    const float* Wr    = (const float*)d_in[4];   // [2R*D, Q]
    const float* br    = (const float*)d_in[5];   // [2R*D]
    const float* Wlin  = (const float*)d_in[6];   // [D, 13D]
    const float* blin  = (const float*)d_in[7];   // [D]
    const int*   ei    = (const int*)d_in[8];     // edge_index [2,E] int32
    const int*   ea    = (const int*)d_in[9];     // edge_attr [E] int32
    float*       out   = (float*)d_out;           // [N,D]

    cudaFuncSetAttribute(gemm_simt, cudaFuncAttributeMaxDynamicSharedMemorySize,
                         SMEM_BYTES);

    rel_kernel  <<<(RELSZ * 32 + 255) / 256, 256>>>(Wr, br, query);
    scan_kernel <<<1, 1024>>>(deg);
    fill_kernel <<<(EE + 255) / 256, 256>>>(ei, ea);
    wperm_kernel<<<NKT, 256>>>(Wlin);
    agg_kernel  <<<(NN * 32 + 255) / 256, 256>>>(nf, bnd, deg);
    gemm_simt   <<<(NN + 127) / 128, 256, SMEM_BYTES>>>(nf, blin, out);
}

// round 9
// speedup vs baseline: 1.1850x; 1.0443x over previous
#include <cuda_runtime.h>
#include <math.h>
#include <stdint.h>

#define NN    50000
#define EE    600000
#define DD    128
#define RREL2 474          /* 2R */
#define QQ    128
#define KTOT  1664         /* 13*D */
#define RELSZ (RREL2*DD)   /* 60672 */
#define NKT   52           /* K tiles of 32 */

// -------- scratch (static device globals; no allocation allowed) --------
__device__ __align__(16) float    g_rel[RELSZ];
__device__ int      g_row_start[NN + 1];
__device__ int      g_cursor[NN];
__device__ unsigned g_packed[EE];                 // src (16b) | attr<<16
__device__ __align__(16) float    g_feat4[(size_t)NN * 4 * DD]; // F [N,512]
__device__ float    g_logdeg[NN];
__device__ float    g_logdeg_mean;
// Wlin permuted to grouped-K, tile-major [kt][k][j], fp32:
__device__ __align__(16) float    g_wB[NKT * 4096];

// ========================= helpers ==========================
__device__ __forceinline__ void fma2(unsigned long long& d,
                                     unsigned long long a, unsigned long long b) {
    asm("fma.rn.f32x2 %0, %1, %2, %0;" : "+l"(d) : "l"(a), "l"(b));
}
__device__ __forceinline__ unsigned long long splat2(float x) {
    unsigned long long r;
    asm("mov.b64 %0, {%1, %1};" : "=l"(r) : "f"(x));
    return r;
}
__device__ __forceinline__ float2 unpack2(unsigned long long v) {
    float2 r;
    asm("mov.b64 {%0, %1}, %2;" : "=f"(r.x), "=f"(r.y) : "l"(v));
    return r;
}
__device__ __forceinline__ uint32_t smem_u32(const void* p) {
    uint32_t a;
    asm("{ .reg .u64 t; cvta.to.shared.u64 t, %1; cvt.u32.u64 %0, t; }"
        : "=r"(a) : "l"(p));
    return a;
}
__device__ __forceinline__ void cp16(uint32_t s, const void* g) {
    asm volatile("cp.async.cg.shared.global [%0], [%1], 16;" :: "r"(s), "l"(g));
}
#define CP_COMMIT() asm volatile("cp.async.commit_group;" ::: "memory")
#define CP_WAIT0()  asm volatile("cp.async.wait_group 0;" ::: "memory")

// ======================= K1: rel = query @ Wr^T + br =======================
__global__ void rel_kernel(const float* __restrict__ Wr,
                           const float* __restrict__ br,
                           const float* __restrict__ query) {
    int warp = (blockIdx.x * blockDim.x + threadIdx.x) >> 5;
    int lane = threadIdx.x & 31;
    if (warp >= RELSZ) return;
    const float* w = Wr + (size_t)warp * QQ;
    float s = w[lane]      * __ldg(&query[lane])
            + w[lane + 32] * __ldg(&query[lane + 32])
            + w[lane + 64] * __ldg(&query[lane + 64])
            + w[lane + 96] * __ldg(&query[lane + 96]);
    #pragma unroll
    for (int o = 16; o; o >>= 1) s += __shfl_xor_sync(0xffffffffu, s, o);
    if (lane == 0) g_rel[warp] = s + br[warp];
}

// ==== K2: exclusive scan of degree -> row_start/cursor, + logdeg & mean ====
__global__ void scan_kernel(const float* __restrict__ degout) {
    __shared__ int   wsum[32];
    __shared__ int   carry;
    __shared__ float fsh[1024];
    int t = threadIdx.x, lane = t & 31, w = t >> 5;
    if (t == 0) carry = 0;
    float lsum = 0.f;
    __syncthreads();
    for (int base = 0; base < NN; base += 1024) {
        int i = base + t;
        float dgf = (i < NN) ? degout[i] : 0.f;
        if (i < NN) {
            float ld = logf(dgf + 1.0f);
            g_logdeg[i] = ld;
            lsum += ld;
        }
        int v = (i < NN) ? (int)(dgf + 0.5f) : 0;
        int x = v;
        #pragma unroll
        for (int o = 1; o < 32; o <<= 1) {
            int y = __shfl_up_sync(0xffffffffu, x, o);
            if (lane >= o) x += y;
        }
        if (lane == 31) wsum[w] = x;
        __syncthreads();
        if (w == 0) {
            int s = wsum[lane];
            #pragma unroll
            for (int o = 1; o < 32; o <<= 1) {
                int y = __shfl_up_sync(0xffffffffu, s, o);
                if (lane >= o) s += y;
            }
            wsum[lane] = s;
        }
        __syncthreads();
        int excl = x - v + (w ? wsum[w - 1] : 0) + carry;
        if (i < NN) { g_row_start[i] = excl; g_cursor[i] = excl; }
        __syncthreads();
        if (t == 1023) carry = excl + v;
        __syncthreads();
    }
    if (t == 0) g_row_start[NN] = carry;
    // block-wide mean of logdeg
    fsh[t] = lsum;
    __syncthreads();
    for (int o = 512; o; o >>= 1) {
        if (t < o) fsh[t] += fsh[t + o];
        __syncthreads();
    }
    if (t == 0) g_logdeg_mean = fsh[0] / (float)NN;
}

// ================= K3: bucket edges into CSR slots ========================
__global__ void fill_kernel(const int* __restrict__ ei,
                            const int* __restrict__ ea) {
    int e = blockIdx.x * blockDim.x + threadIdx.x;
    if (e >= EE) return;
    int src = ei[e];
    int dst = ei[EE + e];
    int a   = ea[e];
    int pos = atomicAdd(&g_cursor[dst], 1);
    g_packed[pos] = (unsigned)src | ((unsigned)a << 16);
}

// ===== K4: permute Wlin to grouped-K tile-major [kt][k][j], fp32 =====
// grouped col cp: cp<128 -> c=cp ; else m=cp-128, s=m>>9, fidx=m&511, c=128+3*fidx+s
__global__ void wperm_kernel(const float* __restrict__ Wlin) {
    __shared__ float tmp[32 * 129];
    int kt = blockIdx.x;
    int t  = threadIdx.x;
    #pragma unroll
    for (int i = 0; i < 16; i++) {
        int e  = t + i * 256;          // 0..4095
        int j  = e >> 5;
        int kl = e & 31;
        int cp = kt * 32 + kl;
        int c;
        if (cp < 128) c = cp;
        else { int m = cp - 128; int s = m >> 9; int f = m & 511; c = 128 + 3 * f + s; }
        tmp[kl * 129 + j] = Wlin[(size_t)j * KTOT + c];
    }
    __syncthreads();
    #pragma unroll
    for (int i = 0; i < 16; i++) {
        int e = t + i * 256;
        g_wB[(size_t)kt * 4096 + e] = tmp[(e >> 7) * 129 + (e & 127)];
    }
}

// ====== K5: per-node gather reduction, float4 per lane (cols 4l..4l+3) ======
__global__ void agg_kernel(const float* __restrict__ nf,
                           const float* __restrict__ boundary,
                           const float* __restrict__ degout) {
    int n    = (blockIdx.x * blockDim.x + threadIdx.x) >> 5;
    int lane = threadIdx.x & 31;
    if (n >= NN) return;
    int beg = g_row_start[n], end = g_row_start[n + 1];
    int c0 = lane * 4;

    float4 sum = make_float4(0.f, 0.f, 0.f, 0.f);
    float4 sq  = make_float4(0.f, 0.f, 0.f, 0.f);
    float4 mx  = make_float4(-INFINITY, -INFINITY, -INFINITY, -INFINITY);
    float4 mn  = make_float4(INFINITY, INFINITY, INFINITY, INFINITY);

    for (int e = beg; e < end; e++) {
        unsigned p = g_packed[e];
        float4 s4 = *(const float4*)(nf    + (size_t)(p & 0xFFFFu) * DD + c0);
        float4 f4 = *(const float4*)(g_rel + (size_t)(p >> 16) * DD + c0);
        float m0 = s4.x * f4.x, m1 = s4.y * f4.y, m2 = s4.z * f4.z, m3 = s4.w * f4.w;
        sum.x += m0; sum.y += m1; sum.z += m2; sum.w += m3;
        sq.x += m0 * m0; sq.y += m1 * m1; sq.z += m2 * m2; sq.w += m3 * m3;
        mx.x = fmaxf(mx.x, m0); mx.y = fmaxf(mx.y, m1);
        mx.z = fmaxf(mx.z, m2); mx.w = fmaxf(mx.w, m3);
        mn.x = fminf(mn.x, m0); mn.y = fminf(mn.y, m1);
        mn.z = fminf(mn.z, m2); mn.w = fminf(mn.w, m3);
    }

    float d0  = degout[n];
    float deg = d0 + 1.0f;
    bool  has_edge = (d0 > 0.0f);
    float inv = 1.0f / deg;
    float4 b = *(const float4*)(boundary + (size_t)n * DD + c0);

    float sums[4] = {sum.x, sum.y, sum.z, sum.w};
    float sqs[4]  = {sq.x, sq.y, sq.z, sq.w};
    float mxs[4]  = {mx.x, mx.y, mx.z, mx.w};
    float mns[4]  = {mn.x, mn.y, mn.z, mn.w};
    float bs[4]   = {b.x, b.y, b.z, b.w};

    #pragma unroll
    for (int u = 0; u < 4; u++) {
        float bb = bs[u];
        float mean   = (sums[u] + bb) * inv;
        float sqmean = (sqs[u] + bb * bb) * inv;
        float vmx = has_edge ? mxs[u] : 0.0f;
        float vmn = has_edge ? mns[u] : 0.0f;
        vmx = fmaxf(vmx, bb);
        vmn = fminf(vmn, bb);
        float sd = sqrtf(fmaxf(sqmean - mean * mean, 1e-6f));
        float4 v = make_float4(mean, vmx, vmn, sd);
        *(float4*)&g_feat4[(size_t)n * 512 + (c0 + u) * 4] = v;
    }
}

// ================== K6: SIMT f32x2 GEMM, fused epilogue =====================
// 128x128 tile, BK=32, 256 threads, 8x8 per thread (j-packed f32x2 accs).
// R5 inner loop (splat-in-loop). BOTH A and B double-buffered -> single
// __syncthreads per k-tile; stA overlaps MMA tail. No minblocks reg cap.
#define ASTR 36
#define AS_F   (128 * ASTR)       /* floats per A buffer (4608) */
#define SM_AS  8192               /* Bs: 2 x 4096 floats        */
#define SM_SC  (SM_AS + 2 * AS_F)
#define SMEM_F (SM_SC + 256)
#define SMEM_BYTES (SMEM_F * 4)

__global__ void __launch_bounds__(256)
gemm_simt(const float* __restrict__ nf,
          const float* __restrict__ blin,
          float* __restrict__ out) {
    extern __shared__ float sm[];
    float* Bs  = sm;                 // [2][32*128]
    float* As  = sm + SM_AS;         // [2][128][ASTR]
    float* sc1 = sm + SM_SC;
    float* sc2 = sc1 + 128;

    const int t  = threadIdx.x;
    const int n0 = blockIdx.x * 128;
    const int tx = t & 15;
    const int ty = t >> 4;
    const int cq = t & 7;            // c-quad for A build
    const int nl = t >> 3;           // base n_local for A build (stride 32 over i)

    if (t < 128) {
        int n = n0 + t;
        float scale = 0.f;
        if (n < NN) scale = g_logdeg[n] / (g_logdeg_mean + 1e-10f);
        sc1[t] = scale;
        sc2[t] = 1.0f / fmaxf(scale, 0.01f);
    }
    __syncthreads();

    const uint32_t bsAddr = smem_u32(Bs);

    // ---- A tile prefetch into registers (grouped-K virtual X) ----
    float4 av[4];
    auto ldA = [&](int kt) {
        int grp = (kt >= 36) ? 3 : (kt >= 20) ? 2 : (kt >= 4) ? 1 : 0;
        #pragma unroll
        for (int i = 0; i < 4; i++) {
            int nli = nl + i * 32;
            int n = n0 + nli;
            float4 v = make_float4(0.f, 0.f, 0.f, 0.f);
            if (n < NN) {
                if (grp == 0) {
                    v = *(const float4*)&nf[(size_t)n * DD + kt * 32 + cq * 4];
                } else {
                    int f0 = kt * 32 - ((grp == 3) ? 1152 : (grp == 2) ? 640 : 128);
                    v = *(const float4*)&g_feat4[(size_t)n * 512 + f0 + cq * 4];
                    if (grp >= 2) {
                        float s = (grp == 3) ? sc2[nli] : sc1[nli];
                        v.x *= s; v.y *= s; v.z *= s; v.w *= s;
                    }
                }
            }
            av[i] = v;
        }
    };
    auto stA = [&](int buf) {
        float* dst = As + buf * AS_F;
        #pragma unroll
        for (int i = 0; i < 4; i++)
            *(float4*)&dst[(nl + i * 32) * ASTR + cq * 4] = av[i];
    };
    auto ldB = [&](int kt, int buf) {
        const float* src = &g_wB[(size_t)kt * 4096];
        uint32_t dst = bsAddr + buf * 16384 + t * 16;
        #pragma unroll
        for (int i = 0; i < 4; i++)
            cp16(dst + i * 4096, src + t * 4 + i * 1024);
        CP_COMMIT();
    };

    unsigned long long acc[8][4];
    #pragma unroll
    for (int r = 0; r < 8; r++)
        #pragma unroll
        for (int p = 0; p < 4; p++) acc[r][p] = 0ull;

    ldA(0);
    ldB(0, 0);
    stA(0);
    CP_WAIT0();
    __syncthreads();

    int cur = 0;
    for (int kt = 0; kt < NKT; kt++) {
        if (kt + 1 < NKT) {
            ldA(kt + 1);
            ldB(kt + 1, cur ^ 1);
        }
        const float* Ac = As + cur * AS_F;
        const float* Bc = Bs + cur * 4096;
        #pragma unroll 4
        for (int kl = 0; kl < 32; kl++) {
            unsigned long long a2[8];
            #pragma unroll
            for (int r = 0; r < 4; r++) {
                a2[r]     = splat2(Ac[(ty * 4 + r) * ASTR + kl]);
                a2[r + 4] = splat2(Ac[(ty * 4 + 64 + r) * ASTR + kl]);
            }
            ulonglong2 b01 = *(const ulonglong2*)&Bc[kl * 128 + tx * 4];
            ulonglong2 b23 = *(const ulonglong2*)&Bc[kl * 128 + tx * 4 + 64];
            #pragma unroll
            for (int r = 0; r < 8; r++) {
                fma2(acc[r][0], a2[r], b01.x);
                fma2(acc[r][1], a2[r], b01.y);
                fma2(acc[r][2], a2[r], b23.x);
                fma2(acc[r][3], a2[r], b23.y);
            }
        }
        if (kt + 1 < NKT) {
            stA(cur ^ 1);          // writes next buffer (readers retired last sync)
            CP_WAIT0();
        }
        __syncthreads();           // one barrier per k-tile
        cur ^= 1;
    }

    // ---- epilogue: bias + relu ----
    float4 bl0 = __ldg((const float4*)&blin[tx * 4]);
    float4 bl1 = __ldg((const float4*)&blin[tx * 4 + 64]);
    #pragma unroll
    for (int r = 0; r < 8; r++) {
        int n = n0 + ty * 4 + ((r < 4) ? r : (64 + r - 4));
        if (n >= NN) continue;
        float2 p0 = unpack2(acc[r][0]);
        float2 p1 = unpack2(acc[r][1]);
        float2 p2 = unpack2(acc[r][2]);
        float2 p3 = unpack2(acc[r][3]);
        float4 o0, o1;
        o0.x = fmaxf(p0.x + bl0.x, 0.f);
        o0.y = fmaxf(p0.y + bl0.y, 0.f);
        o0.z = fmaxf(p1.x + bl0.z, 0.f);
        o0.w = fmaxf(p1.y + bl0.w, 0.f);
        o1.x = fmaxf(p2.x + bl1.x, 0.f);
        o1.y = fmaxf(p2.y + bl1.y, 0.f);
        o1.z = fmaxf(p3.x + bl1.z, 0.f);
        o1.w = fmaxf(p3.y + bl1.w, 0.f);
        *(float4*)&out[(size_t)n * DD + tx * 4]      = o0;
        *(float4*)&out[(size_t)n * DD + tx * 4 + 64] = o1;
    }
}

// ============================== launch ====================================
extern "C" void kernel_launch(void* const* d_in, const int* in_sizes, int n_in,
                              void* d_out, int out_size) {
    const float* nf    = (const float*)d_in[0];   // node_features [N,D]
    const float* query = (const float*)d_in[1];   // [1,Q]
    const float* bnd   = (const float*)d_in[2];   // boundary [N,D]
    const float* deg   = (const float*)d_in[3];   // degree_out [N]
    const float* Wr    = (const float*)d_in[4];   // [2R*D, Q]
    const float* br    = (const float*)d_in[5];   // [2R*D]
    const float* Wlin  = (const float*)d_in[6];   // [D, 13D]
    const float* blin  = (const float*)d_in[7];   // [D]
    const int*   ei    = (const int*)d_in[8];     // edge_index [2,E] int32
    const int*   ea    = (const int*)d_in[9];     // edge_attr [E] int32
    float*       out   = (float*)d_out;           // [N,D]

    cudaFuncSetAttribute(gemm_simt, cudaFuncAttributeMaxDynamicSharedMemorySize,
                         SMEM_BYTES);

    rel_kernel  <<<(RELSZ * 32 + 255) / 256, 256>>>(Wr, br, query);
    scan_kernel <<<1, 1024>>>(deg);
    fill_kernel <<<(EE + 255) / 256, 256>>>(ei, ea);
    wperm_kernel<<<NKT, 256>>>(Wlin);
    agg_kernel  <<<(NN * 32 + 255) / 256, 256>>>(nf, bnd, deg);
    gemm_simt   <<<(NN + 127) / 128, 256, SMEM_BYTES>>>(nf, blin, out);
}

// round 10
// speedup vs baseline: 1.2501x; 1.0550x over previous
#include <cuda_runtime.h>
#include <math.h>
#include <stdint.h>

#define NN    50000
#define EE    600000
#define DD    128
#define RREL2 474          /* 2R */
#define QQ    128
#define KTOT  1664         /* 13*D */
#define RELSZ (RREL2*DD)   /* 60672 */
#define NKT   52           /* K tiles of 32 */
#define NBLK  196          /* scan blocks of 256 */

// -------- scratch (static device globals; no allocation allowed) --------
__device__ __align__(16) float    g_rel[RELSZ];
__device__ int      g_row_start[NN + 1];
__device__ int      g_cursor[NN];
__device__ unsigned g_packed[EE];                 // src (16b) | attr<<16
__device__ __align__(16) float    g_feat4[(size_t)NN * 4 * DD]; // F [N,512]
__device__ float    g_logdeg[NN];
__device__ float    g_logdeg_mean;
__device__ int      g_bsum[256];
__device__ float    g_lsum[256];
__device__ int      g_boff[256];
// Wlin permuted to grouped-K, tile-major [kt][k][j], fp32:
__device__ __align__(16) float    g_wB[NKT * 4096];

// ========================= helpers ==========================
__device__ __forceinline__ void fma2(unsigned long long& d,
                                     unsigned long long a, unsigned long long b) {
    asm("fma.rn.f32x2 %0, %1, %2, %0;" : "+l"(d) : "l"(a), "l"(b));
}
__device__ __forceinline__ unsigned long long splat2(float x) {
    unsigned long long r;
    asm("mov.b64 %0, {%1, %1};" : "=l"(r) : "f"(x));
    return r;
}
__device__ __forceinline__ float2 unpack2(unsigned long long v) {
    float2 r;
    asm("mov.b64 {%0, %1}, %2;" : "=f"(r.x), "=f"(r.y) : "l"(v));
    return r;
}
__device__ __forceinline__ uint32_t smem_u32(const void* p) {
    uint32_t a;
    asm("{ .reg .u64 t; cvta.to.shared.u64 t, %1; cvt.u32.u64 %0, t; }"
        : "=r"(a) : "l"(p));
    return a;
}
__device__ __forceinline__ void cp16(uint32_t s, const void* g) {
    asm volatile("cp.async.cg.shared.global [%0], [%1], 16;" :: "r"(s), "l"(g));
}
#define CP_COMMIT() asm volatile("cp.async.commit_group;" ::: "memory")
#define CP_WAIT0()  asm volatile("cp.async.wait_group 0;" ::: "memory")

// ======================= K1: rel = query @ Wr^T + br =======================
__global__ void rel_kernel(const float* __restrict__ Wr,
                           const float* __restrict__ br,
                           const float* __restrict__ query) {
    int warp = (blockIdx.x * blockDim.x + threadIdx.x) >> 5;
    int lane = threadIdx.x & 31;
    if (warp >= RELSZ) return;
    const float* w = Wr + (size_t)warp * QQ;
    float s = w[lane]      * __ldg(&query[lane])
            + w[lane + 32] * __ldg(&query[lane + 32])
            + w[lane + 64] * __ldg(&query[lane + 64])
            + w[lane + 96] * __ldg(&query[lane + 96]);
    #pragma unroll
    for (int o = 16; o; o >>= 1) s += __shfl_xor_sync(0xffffffffu, s, o);
    if (lane == 0) g_rel[warp] = s + br[warp];
}

// ==== K2a: per-block sums of int(degree) + logdeg + logdeg partial sums ====
__global__ void scan1_kernel(const float* __restrict__ degout) {
    int b = blockIdx.x, t = threadIdx.x, i = b * 256 + t;
    int lane = t & 31, w = t >> 5;
    float dgf = (i < NN) ? degout[i] : 0.f;
    int   v   = (i < NN) ? (int)(dgf + 0.5f) : 0;
    float ld  = (i < NN) ? logf(dgf + 1.0f) : 0.f;
    if (i < NN) g_logdeg[i] = ld;
    __shared__ int   ish[8];
    __shared__ float fsh[8];
    int s = v; float f = ld;
    #pragma unroll
    for (int o = 16; o; o >>= 1) {
        s += __shfl_xor_sync(0xffffffffu, s, o);
        f += __shfl_xor_sync(0xffffffffu, f, o);
    }
    if (lane == 0) { ish[w] = s; fsh[w] = f; }
    __syncthreads();
    if (t == 0) {
        int S = 0; float F = 0.f;
        #pragma unroll
        for (int j = 0; j < 8; j++) { S += ish[j]; F += fsh[j]; }
        g_bsum[b] = S; g_lsum[b] = F;
    }
}

// ==== K2b: 1-block exclusive scan of block sums + logdeg mean ====
__global__ void scan2_kernel() {
    int t = threadIdx.x, lane = t & 31, w = t >> 5;
    __shared__ int   wsh[8];
    __shared__ float fsh[8];
    int   v = (t < NBLK) ? g_bsum[t] : 0;
    float f = (t < NBLK) ? g_lsum[t] : 0.f;
    int x = v;
    #pragma unroll
    for (int o = 1; o < 32; o <<= 1) {
        int y = __shfl_up_sync(0xffffffffu, x, o);
        if (lane >= o) x += y;
    }
    #pragma unroll
    for (int o = 16; o; o >>= 1) f += __shfl_xor_sync(0xffffffffu, f, o);
    if (lane == 31) wsh[w] = x;
    if (lane == 0)  fsh[w] = f;
    __syncthreads();
    if (t == 0) {
        int c = 0;
        #pragma unroll
        for (int j = 0; j < 8; j++) { int tmp = wsh[j]; wsh[j] = c; c += tmp; }
        g_row_start[NN] = c;                 // total edges
        float F = 0.f;
        #pragma unroll
        for (int j = 0; j < 8; j++) F += fsh[j];
        g_logdeg_mean = F / (float)NN;
    }
    __syncthreads();
    if (t < NBLK) g_boff[t] = x - v + wsh[w];
}

// ==== K2c: per-block rescan + global offset -> row_start, cursor ====
__global__ void scan3_kernel(const float* __restrict__ degout) {
    int b = blockIdx.x, t = threadIdx.x, i = b * 256 + t;
    int lane = t & 31, w = t >> 5;
    __shared__ int wsh[8];
    int v = (i < NN) ? (int)(degout[i] + 0.5f) : 0;
    int x = v;
    #pragma unroll
    for (int o = 1; o < 32; o <<= 1) {
        int y = __shfl_up_sync(0xffffffffu, x, o);
        if (lane >= o) x += y;
    }
    if (lane == 31) wsh[w] = x;
    __syncthreads();
    if (t == 0) {
        int c = 0;
        #pragma unroll
        for (int j = 0; j < 8; j++) { int tmp = wsh[j]; wsh[j] = c; c += tmp; }
    }
    __syncthreads();
    if (i < NN) {
        int excl = x - v + wsh[w] + g_boff[b];
        g_row_start[i] = excl;
        g_cursor[i]    = excl;
    }
}

// ================= K3: bucket edges into CSR slots ========================
__global__ void fill_kernel(const int* __restrict__ ei,
                            const int* __restrict__ ea) {
    int e = blockIdx.x * blockDim.x + threadIdx.x;
    if (e >= EE) return;
    int src = ei[e];
    int dst = ei[EE + e];
    int a   = ea[e];
    int pos = atomicAdd(&g_cursor[dst], 1);
    g_packed[pos] = (unsigned)src | ((unsigned)a << 16);
}

// ===== K4: permute Wlin to grouped-K tile-major [kt][k][j], fp32 =====
__global__ void wperm_kernel(const float* __restrict__ Wlin) {
    __shared__ float tmp[32 * 129];
    int kt = blockIdx.x;
    int t  = threadIdx.x;
    #pragma unroll
    for (int i = 0; i < 16; i++) {
        int e  = t + i * 256;          // 0..4095
        int j  = e >> 5;
        int kl = e & 31;
        int cp = kt * 32 + kl;
        int c;
        if (cp < 128) c = cp;
        else { int m = cp - 128; int s = m >> 9; int f = m & 511; c = 128 + 3 * f + s; }
        tmp[kl * 129 + j] = Wlin[(size_t)j * KTOT + c];
    }
    __syncthreads();
    #pragma unroll
    for (int i = 0; i < 16; i++) {
        int e = t + i * 256;
        g_wB[(size_t)kt * 4096 + e] = tmp[(e >> 7) * 129 + (e & 127)];
    }
}

// ====== K5: per-node gather reduction, 2-way edge unroll for MLP ======
__global__ void agg_kernel(const float* __restrict__ nf,
                           const float* __restrict__ boundary,
                           const float* __restrict__ degout) {
    int n    = (blockIdx.x * blockDim.x + threadIdx.x) >> 5;
    int lane = threadIdx.x & 31;
    if (n >= NN) return;
    int beg = g_row_start[n], end = g_row_start[n + 1];
    int c0 = lane * 4;

    float4 sum = make_float4(0.f, 0.f, 0.f, 0.f);
    float4 sq  = make_float4(0.f, 0.f, 0.f, 0.f);
    float4 mx  = make_float4(-INFINITY, -INFINITY, -INFINITY, -INFINITY);
    float4 mn  = make_float4(INFINITY, INFINITY, INFINITY, INFINITY);

    int e = beg;
    for (; e + 1 < end; e += 2) {
        unsigned p0 = g_packed[e];
        unsigned p1 = g_packed[e + 1];
        float4 s40 = *(const float4*)(nf    + (size_t)(p0 & 0xFFFFu) * DD + c0);
        float4 f40 = *(const float4*)(g_rel + (size_t)(p0 >> 16) * DD + c0);
        float4 s41 = *(const float4*)(nf    + (size_t)(p1 & 0xFFFFu) * DD + c0);
        float4 f41 = *(const float4*)(g_rel + (size_t)(p1 >> 16) * DD + c0);
        float a0 = s40.x * f40.x, a1 = s40.y * f40.y, a2 = s40.z * f40.z, a3 = s40.w * f40.w;
        float b0 = s41.x * f41.x, b1 = s41.y * f41.y, b2 = s41.z * f41.z, b3 = s41.w * f41.w;
        sum.x += a0 + b0; sum.y += a1 + b1; sum.z += a2 + b2; sum.w += a3 + b3;
        sq.x += a0 * a0 + b0 * b0; sq.y += a1 * a1 + b1 * b1;
        sq.z += a2 * a2 + b2 * b2; sq.w += a3 * a3 + b3 * b3;
        mx.x = fmaxf(mx.x, fmaxf(a0, b0)); mx.y = fmaxf(mx.y, fmaxf(a1, b1));
        mx.z = fmaxf(mx.z, fmaxf(a2, b2)); mx.w = fmaxf(mx.w, fmaxf(a3, b3));
        mn.x = fminf(mn.x, fminf(a0, b0)); mn.y = fminf(mn.y, fminf(a1, b1));
        mn.z = fminf(mn.z, fminf(a2, b2)); mn.w = fminf(mn.w, fminf(a3, b3));
    }
    if (e < end) {
        unsigned p = g_packed[e];
        float4 s4 = *(const float4*)(nf    + (size_t)(p & 0xFFFFu) * DD + c0);
        float4 f4 = *(const float4*)(g_rel + (size_t)(p >> 16) * DD + c0);
        float m0 = s4.x * f4.x, m1 = s4.y * f4.y, m2 = s4.z * f4.z, m3 = s4.w * f4.w;
        sum.x += m0; sum.y += m1; sum.z += m2; sum.w += m3;
        sq.x += m0 * m0; sq.y += m1 * m1; sq.z += m2 * m2; sq.w += m3 * m3;
        mx.x = fmaxf(mx.x, m0); mx.y = fmaxf(mx.y, m1);
        mx.z = fmaxf(mx.z, m2); mx.w = fmaxf(mx.w, m3);
        mn.x = fminf(mn.x, m0); mn.y = fminf(mn.y, m1);
        mn.z = fminf(mn.z, m2); mn.w = fminf(mn.w, m3);
    }

    float d0  = degout[n];
    float deg = d0 + 1.0f;
    bool  has_edge = (d0 > 0.0f);
    float inv = 1.0f / deg;
    float4 b = *(const float4*)(boundary + (size_t)n * DD + c0);

    float sums[4] = {sum.x, sum.y, sum.z, sum.w};
    float sqs[4]  = {sq.x, sq.y, sq.z, sq.w};
    float mxs[4]  = {mx.x, mx.y, mx.z, mx.w};
    float mns[4]  = {mn.x, mn.y, mn.z, mn.w};
    float bs[4]   = {b.x, b.y, b.z, b.w};

    #pragma unroll
    for (int u = 0; u < 4; u++) {
        float bb = bs[u];
        float mean   = (sums[u] + bb) * inv;
        float sqmean = (sqs[u] + bb * bb) * inv;
        float vmx = has_edge ? mxs[u] : 0.0f;
        float vmn = has_edge ? mns[u] : 0.0f;
        vmx = fmaxf(vmx, bb);
        vmn = fminf(vmn, bb);
        float sd = sqrtf(fmaxf(sqmean - mean * mean, 1e-6f));
        float4 v = make_float4(mean, vmx, vmn, sd);
        *(float4*)&g_feat4[(size_t)n * 512 + (c0 + u) * 4] = v;
    }
}

// ================== K6: SIMT f32x2 GEMM, fused epilogue =====================
// 128x128 tile, BK=32, 256 threads, 8x8 per thread (j-packed f32x2 accs).
// A/B double-buffered, single barrier per k-tile. A loads kl-PAIRED (LDS.64).
#define ASTR 36
#define AS_F   (128 * ASTR)       /* floats per A buffer (4608) */
#define SM_AS  8192               /* Bs: 2 x 4096 floats        */
#define SM_SC  (SM_AS + 2 * AS_F)
#define SMEM_F (SM_SC + 256)
#define SMEM_BYTES (SMEM_F * 4)

__global__ void __launch_bounds__(256)
gemm_simt(const float* __restrict__ nf,
          const float* __restrict__ blin,
          float* __restrict__ out) {
    extern __shared__ float sm[];
    float* Bs  = sm;                 // [2][32*128]
    float* As  = sm + SM_AS;         // [2][128][ASTR]
    float* sc1 = sm + SM_SC;
    float* sc2 = sc1 + 128;

    const int t  = threadIdx.x;
    const int n0 = blockIdx.x * 128;
    const int tx = t & 15;
    const int ty = t >> 4;
    const int cq = t & 7;            // c-quad for A build
    const int nl = t >> 3;           // base n_local for A build (stride 32 over i)

    if (t < 128) {
        int n = n0 + t;
        float scale = 0.f;
        if (n < NN) scale = g_logdeg[n] / (g_logdeg_mean + 1e-10f);
        sc1[t] = scale;
        sc2[t] = 1.0f / fmaxf(scale, 0.01f);
    }
    __syncthreads();

    const uint32_t bsAddr = smem_u32(Bs);

    float4 av[4];
    auto ldA = [&](int kt) {
        int grp = (kt >= 36) ? 3 : (kt >= 20) ? 2 : (kt >= 4) ? 1 : 0;
        #pragma unroll
        for (int i = 0; i < 4; i++) {
            int nli = nl + i * 32;
            int n = n0 + nli;
            float4 v = make_float4(0.f, 0.f, 0.f, 0.f);
            if (n < NN) {
                if (grp == 0) {
                    v = *(const float4*)&nf[(size_t)n * DD + kt * 32 + cq * 4];
                } else {
                    int f0 = kt * 32 - ((grp == 3) ? 1152 : (grp == 2) ? 640 : 128);
                    v = *(const float4*)&g_feat4[(size_t)n * 512 + f0 + cq * 4];
                    if (grp >= 2) {
                        float s = (grp == 3) ? sc2[nli] : sc1[nli];
                        v.x *= s; v.y *= s; v.z *= s; v.w *= s;
                    }
                }
            }
            av[i] = v;
        }
    };
    auto stA = [&](int buf) {
        float* dst = As + buf * AS_F;
        #pragma unroll
        for (int i = 0; i < 4; i++)
            *(float4*)&dst[(nl + i * 32) * ASTR + cq * 4] = av[i];
    };
    auto ldB = [&](int kt, int buf) {
        const float* src = &g_wB[(size_t)kt * 4096];
        uint32_t dst = bsAddr + buf * 16384 + t * 16;
        #pragma unroll
        for (int i = 0; i < 4; i++)
            cp16(dst + i * 4096, src + t * 4 + i * 1024);
        CP_COMMIT();
    };

    unsigned long long acc[8][4];
    #pragma unroll
    for (int r = 0; r < 8; r++)
        #pragma unroll
        for (int p = 0; p < 4; p++) acc[r][p] = 0ull;

    ldA(0);
    ldB(0, 0);
    stA(0);
    CP_WAIT0();
    __syncthreads();

    int cur = 0;
    for (int kt = 0; kt < NKT; kt++) {
        if (kt + 1 < NKT) {
            ldA(kt + 1);
            ldB(kt + 1, cur ^ 1);
        }
        const float* Ac = As + cur * AS_F;
        const float* Bc = Bs + cur * 4096;
        #pragma unroll 2
        for (int klp = 0; klp < 32; klp += 2) {
            float2 a0[8];
            #pragma unroll
            for (int r = 0; r < 4; r++) {
                a0[r]     = *(const float2*)&Ac[(ty * 4 + r) * ASTR + klp];
                a0[r + 4] = *(const float2*)&Ac[(ty * 4 + 64 + r) * ASTR + klp];
            }
            #pragma unroll
            for (int sub = 0; sub < 2; sub++) {
                int kl = klp + sub;
                unsigned long long a2[8];
                #pragma unroll
                for (int r = 0; r < 8; r++)
                    a2[r] = splat2(sub ? a0[r].y : a0[r].x);
                ulonglong2 b01 = *(const ulonglong2*)&Bc[kl * 128 + tx * 4];
                ulonglong2 b23 = *(const ulonglong2*)&Bc[kl * 128 + tx * 4 + 64];
                #pragma unroll
                for (int r = 0; r < 8; r++) {
                    fma2(acc[r][0], a2[r], b01.x);
                    fma2(acc[r][1], a2[r], b01.y);
                    fma2(acc[r][2], a2[r], b23.x);
                    fma2(acc[r][3], a2[r], b23.y);
                }
            }
        }
        if (kt + 1 < NKT) {
            stA(cur ^ 1);
            CP_WAIT0();
        }
        __syncthreads();
        cur ^= 1;
    }

    // ---- epilogue: bias + relu ----
    float4 bl0 = __ldg((const float4*)&blin[tx * 4]);
    float4 bl1 = __ldg((const float4*)&blin[tx * 4 + 64]);
    #pragma unroll
    for (int r = 0; r < 8; r++) {
        int n = n0 + ty * 4 + ((r < 4) ? r : (64 + r - 4));
        if (n >= NN) continue;
        float2 p0 = unpack2(acc[r][0]);
        float2 p1 = unpack2(acc[r][1]);
        float2 p2 = unpack2(acc[r][2]);
        float2 p3 = unpack2(acc[r][3]);
        float4 o0, o1;
        o0.x = fmaxf(p0.x + bl0.x, 0.f);
        o0.y = fmaxf(p0.y + bl0.y, 0.f);
        o0.z = fmaxf(p1.x + bl0.z, 0.f);
        o0.w = fmaxf(p1.y + bl0.w, 0.f);
        o1.x = fmaxf(p2.x + bl1.x, 0.f);
        o1.y = fmaxf(p2.y + bl1.y, 0.f);
        o1.z = fmaxf(p3.x + bl1.z, 0.f);
        o1.w = fmaxf(p3.y + bl1.w, 0.f);
        *(float4*)&out[(size_t)n * DD + tx * 4]      = o0;
        *(float4*)&out[(size_t)n * DD + tx * 4 + 64] = o1;
    }
}

// ============================== launch ====================================
extern "C" void kernel_launch(void* const* d_in, const int* in_sizes, int n_in,
                              void* d_out, int out_size) {
    const float* nf    = (const float*)d_in[0];   // node_features [N,D]
    const float* query = (const float*)d_in[1];   // [1,Q]
    const float* bnd   = (const float*)d_in[2];   // boundary [N,D]
    const float* deg   = (const float*)d_in[3];   // degree_out [N]
    const float* Wr    = (const float*)d_in[4];   // [2R*D, Q]
    const float* br    = (const float*)d_in[5];   // [2R*D]
    const float* Wlin  = (const float*)d_in[6];   // [D, 13D]
    const float* blin  = (const float*)d_in[7];   // [D]
    const int*   ei    = (const int*)d_in[8];     // edge_index [2,E] int32
    const int*   ea    = (const int*)d_in[9];     // edge_attr [E] int32
    float*       out   = (float*)d_out;           // [N,D]

    cudaFuncSetAttribute(gemm_simt, cudaFuncAttributeMaxDynamicSharedMemorySize,
                         SMEM_BYTES);

    rel_kernel  <<<(RELSZ * 32 + 255) / 256, 256>>>(Wr, br, query);
    scan1_kernel<<<NBLK, 256>>>(deg);
    scan2_kernel<<<1, 256>>>();
    scan3_kernel<<<NBLK, 256>>>(deg);
    fill_kernel <<<(EE + 255) / 256, 256>>>(ei, ea);
    wperm_kernel<<<NKT, 256>>>(Wlin);
    agg_kernel  <<<(NN * 32 + 255) / 256, 256>>>(nf, bnd, deg);
    gemm_simt   <<<(NN + 127) / 128, 256, SMEM_BYTES>>>(nf, blin, out);
}